// round 1
// baseline (speedup 1.0000x reference)
#include <cuda_runtime.h>

#define IMG     512
#define NIMG    32
#define WIN     11
#define HALO    5
#define TILE    32
#define IN_T    (TILE + WIN - 1)   // 42
#define NTHREADS 256

__device__ double g_acc;

__global__ void ssim_zero_kernel() { g_acc = 0.0; }

__global__ void __launch_bounds__(NTHREADS)
ssim_main_kernel(const float* __restrict__ x,
                 const float* __restrict__ y,
                 const float* __restrict__ w)
{
    __shared__ float g[WIN];
    __shared__ float sx[IN_T][IN_T + 2];   // +2 pad: conflict-free row stride 44
    __shared__ float sy[IN_T][IN_T + 2];
    __shared__ float h0[IN_T][TILE];       // h-conv of x
    __shared__ float h1[IN_T][TILE];       // h-conv of y
    __shared__ float h2[IN_T][TILE];       // h-conv of x*x
    __shared__ float h3[IN_T][TILE];       // h-conv of y*y
    __shared__ float h4[IN_T][TILE];       // h-conv of x*y
    __shared__ float warpsum[NTHREADS / 32];

    const int tid = threadIdx.x;

    // Separable 1D kernel: g[i] = sum_j w[i][j]  (exact since sum(g)=1)
    if (tid < WIN) {
        float s = 0.f;
        #pragma unroll
        for (int j = 0; j < WIN; j++) s += w[tid * WIN + j];
        g[tid] = s;
    }

    const int n      = blockIdx.z;
    const int tile_x = blockIdx.x * TILE;
    const int tile_y = blockIdx.y * TILE;
    const float* __restrict__ xb = x + (size_t)n * IMG * IMG;
    const float* __restrict__ yb = y + (size_t)n * IMG * IMG;

    // ---- Load haloed tile, zero-padded outside the image (matches jax zero-pad conv)
    for (int i = tid; i < IN_T * IN_T; i += NTHREADS) {
        const int r  = i / IN_T;
        const int c  = i - r * IN_T;
        const int gr = tile_y + r - HALO;
        const int gc = tile_x + c - HALO;
        float vx = 0.f, vy = 0.f;
        if ((unsigned)gr < IMG && (unsigned)gc < IMG) {
            const int idx = gr * IMG + gc;
            vx = xb[idx];
            vy = yb[idx];
        }
        sx[r][c] = vx;
        sy[r][c] = vy;
    }
    __syncthreads();

    // ---- Horizontal pass: 5 planes at once from the two input tiles
    for (int i = tid; i < IN_T * TILE; i += NTHREADS) {
        const int r = i / TILE;
        const int c = i - r * TILE;
        float ax = 0.f, ay = 0.f, ax2 = 0.f, ay2 = 0.f, axy = 0.f;
        #pragma unroll
        for (int k = 0; k < WIN; k++) {
            const float gv = g[k];
            const float vx = sx[r][c + k];
            const float vy = sy[r][c + k];
            ax  = fmaf(gv, vx,      ax);
            ay  = fmaf(gv, vy,      ay);
            ax2 = fmaf(gv * vx, vx, ax2);
            ay2 = fmaf(gv * vy, vy, ay2);
            axy = fmaf(gv * vx, vy, axy);
        }
        h0[r][c] = ax;
        h1[r][c] = ay;
        h2[r][c] = ax2;
        h3[r][c] = ay2;
        h4[r][c] = axy;
    }
    __syncthreads();

    // ---- Vertical pass + SSIM map + clip, accumulate per-thread
    const float C1  = 1e-4f;    // 0.01^2
    const float C2  = 9e-4f;    // 0.03^2
    const float EPS = 1e-8f;

    float local = 0.f;
    for (int i = tid; i < TILE * TILE; i += NTHREADS) {
        const int r = i / TILE;
        const int c = i - r * TILE;
        float mx = 0.f, my = 0.f, ex2 = 0.f, ey2 = 0.f, exy = 0.f;
        #pragma unroll
        for (int k = 0; k < WIN; k++) {
            const float gv = g[k];
            mx  = fmaf(gv, h0[r + k][c], mx);
            my  = fmaf(gv, h1[r + k][c], my);
            ex2 = fmaf(gv, h2[r + k][c], ex2);
            ey2 = fmaf(gv, h3[r + k][c], ey2);
            exy = fmaf(gv, h4[r + k][c], exy);
        }
        const float mx2 = mx * mx;
        const float my2 = my * my;
        const float mxy = mx * my;
        const float sx2 = ex2 - mx2;
        const float sy2 = ey2 - my2;
        const float sxy = exy - mxy;
        const float num = (2.f * mxy + C1) * (2.f * sxy + C2);
        const float den = (mx2 + my2 + C1) * (sx2 + sy2 + C2);
        float v = num / (den + EPS);
        v = fminf(fmaxf(v, 0.f), 1.f);
        local += v;
    }

    // ---- Block reduction
    #pragma unroll
    for (int off = 16; off; off >>= 1)
        local += __shfl_down_sync(0xffffffffu, local, off);
    if ((tid & 31) == 0) warpsum[tid >> 5] = local;
    __syncthreads();
    if (tid == 0) {
        float s = 0.f;
        #pragma unroll
        for (int i = 0; i < NTHREADS / 32; i++) s += warpsum[i];
        atomicAdd(&g_acc, (double)s);
    }
}

__global__ void ssim_finalize_kernel(float* __restrict__ out) {
    out[0] = (float)(g_acc / ((double)NIMG * IMG * IMG));
}

extern "C" void kernel_launch(void* const* d_in, const int* in_sizes, int n_in,
                              void* d_out, int out_size)
{
    const float* x = (const float*)d_in[0];
    const float* y = (const float*)d_in[1];
    const float* w = (const float*)d_in[2];
    float* out = (float*)d_out;

    ssim_zero_kernel<<<1, 1>>>();
    dim3 grid(IMG / TILE, IMG / TILE, NIMG);   // 16 x 16 x 32 = 8192 CTAs
    ssim_main_kernel<<<grid, NTHREADS>>>(x, y, w);
    ssim_finalize_kernel<<<1, 1>>>(out);
}

// round 2
// speedup vs baseline: 1.0966x; 1.0966x over previous
#include <cuda_runtime.h>

#define IMG     512
#define NIMG    32
#define WIN     11
#define TILE    32
#define IN_T    (TILE + WIN - 1)   // 42
#define NTHREADS 256

typedef unsigned long long u64;

__device__ double g_acc;

__device__ __forceinline__ u64 pack2(float a, float b) {
    u64 r; asm("mov.b64 %0, {%1,%2};" : "=l"(r) : "f"(a), "f"(b)); return r;
}
__device__ __forceinline__ void unpack2(u64 v, float &a, float &b) {
    asm("mov.b64 {%0,%1}, %2;" : "=f"(a), "=f"(b) : "l"(v));
}
__device__ __forceinline__ u64 fma2(u64 a, u64 b, u64 c) {
    u64 d; asm("fma.rn.f32x2 %0, %1, %2, %3;" : "=l"(d) : "l"(a), "l"(b), "l"(c)); return d;
}
__device__ __forceinline__ u64 mul2(u64 a, u64 b) {
    u64 d; asm("mul.rn.f32x2 %0, %1, %2;" : "=l"(d) : "l"(a), "l"(b)); return d;
}

__global__ void ssim_zero_kernel() { g_acc = 0.0; }

__global__ void __launch_bounds__(NTHREADS)
ssim_main_kernel(const float* __restrict__ x,
                 const float* __restrict__ y,
                 const float* __restrict__ w)
{
    __shared__ float g[WIN];
    __shared__ u64   sp[IN_T][IN_T];    // packed {x, y}
    __shared__ u64   hmu[IN_T][TILE];   // h-conv packed {mu_x, mu_y}
    __shared__ u64   hsq[IN_T][TILE];   // h-conv packed {E[x2], E[y2]}
    __shared__ float hxy[IN_T][TILE];   // h-conv E[xy]
    __shared__ float warpsum[NTHREADS / 32];

    const int tid = threadIdx.x;

    // Separable 1D kernel: g[i] = sum_j w[i][j]  (exact: sum(g)=1)
    if (tid < WIN) {
        float s = 0.f;
        #pragma unroll
        for (int j = 0; j < WIN; j++) s += w[tid * WIN + j];
        g[tid] = s;
    }

    const int n      = blockIdx.z;
    const int tile_x = blockIdx.x * TILE;
    const int tile_y = blockIdx.y * TILE;
    const float* __restrict__ xb = x + (size_t)n * IMG * IMG;
    const float* __restrict__ yb = y + (size_t)n * IMG * IMG;

    // ---- Stage A: load haloed tile as packed pairs, zero-padded outside image
    for (int i = tid; i < IN_T * IN_T; i += NTHREADS) {
        const int r  = i / IN_T;
        const int c  = i - r * IN_T;
        const int gr = tile_y + r - (WIN / 2);
        const int gc = tile_x + c - (WIN / 2);
        float vx = 0.f, vy = 0.f;
        if ((unsigned)gr < IMG && (unsigned)gc < IMG) {
            const int idx = gr * IMG + gc;
            vx = xb[idx];
            vy = yb[idx];
        }
        sp[r][c] = pack2(vx, vy);
    }
    __syncthreads();

    // Per-thread copies of the taps (scalar + packed)
    float garr[WIN];
    u64   gg[WIN];
    #pragma unroll
    for (int k = 0; k < WIN; k++) {
        garr[k] = g[k];
        gg[k]   = pack2(garr[k], garr[k]);
    }

    // ---- Stage B: horizontal pass. 42 rows x 4 segments of 8 outputs = 168 threads.
    // Stream 18 inputs, accumulate into 8 outputs (register rolling).
    if (tid < IN_T * 4) {
        const int row = tid >> 2;
        const int s0  = (tid & 3) * 8;

        u64   amu[8], asq[8];
        float axy[8];
        #pragma unroll
        for (int o = 0; o < 8; o++) { amu[o] = 0ull; asq[o] = 0ull; axy[o] = 0.f; }

        #pragma unroll
        for (int i = 0; i < 18; i++) {
            const u64 p  = sp[row][s0 + i];
            const u64 p2 = mul2(p, p);
            float px, py;
            unpack2(p, px, py);
            const float pxy = px * py;
            #pragma unroll
            for (int o = 0; o < 8; o++) {
                const int k = i - o;
                if (k >= 0 && k < WIN) {
                    amu[o] = fma2(gg[k], p,  amu[o]);
                    asq[o] = fma2(gg[k], p2, asq[o]);
                    axy[o] = fmaf(garr[k], pxy, axy[o]);
                }
            }
        }
        #pragma unroll
        for (int o = 0; o < 8; o++) {
            hmu[row][s0 + o] = amu[o];
            hsq[row][s0 + o] = asq[o];
            hxy[row][s0 + o] = axy[o];
        }
    }
    __syncthreads();

    // ---- Stage C: vertical pass + SSIM. 32 cols x 4 segments of 8 rows = 128 threads.
    const float C1  = 1e-4f;    // 0.01^2
    const float C2  = 9e-4f;    // 0.03^2
    const float EPS = 1e-8f;

    float local = 0.f;
    if (tid < TILE * 4) {
        const int col = tid & 31;
        const int r0  = (tid >> 5) * 8;

        u64   vmu[8], vsq[8];
        float vxy[8];
        #pragma unroll
        for (int o = 0; o < 8; o++) { vmu[o] = 0ull; vsq[o] = 0ull; vxy[o] = 0.f; }

        #pragma unroll
        for (int i = 0; i < 18; i++) {
            const u64   m  = hmu[r0 + i][col];
            const u64   q  = hsq[r0 + i][col];
            const float xv = hxy[r0 + i][col];
            #pragma unroll
            for (int o = 0; o < 8; o++) {
                const int k = i - o;
                if (k >= 0 && k < WIN) {
                    vmu[o] = fma2(gg[k], m, vmu[o]);
                    vsq[o] = fma2(gg[k], q, vsq[o]);
                    vxy[o] = fmaf(garr[k], xv, vxy[o]);
                }
            }
        }

        #pragma unroll
        for (int o = 0; o < 8; o++) {
            float mx, my, ex2, ey2;
            unpack2(vmu[o], mx, my);
            unpack2(vsq[o], ex2, ey2);
            const float exy = vxy[o];
            const float mx2 = mx * mx;
            const float my2 = my * my;
            const float mxy = mx * my;
            const float sx2 = ex2 - mx2;
            const float sy2 = ey2 - my2;
            const float sxy = exy - mxy;
            const float num = (2.f * mxy + C1) * (2.f * sxy + C2);
            const float den = (mx2 + my2 + C1) * (sx2 + sy2 + C2);
            float v = num / (den + EPS);
            v = fminf(fmaxf(v, 0.f), 1.f);
            local += v;
        }
    }

    // ---- Block reduction
    #pragma unroll
    for (int off = 16; off; off >>= 1)
        local += __shfl_down_sync(0xffffffffu, local, off);
    if ((tid & 31) == 0) warpsum[tid >> 5] = local;
    __syncthreads();
    if (tid == 0) {
        float s = 0.f;
        #pragma unroll
        for (int i = 0; i < NTHREADS / 32; i++) s += warpsum[i];
        atomicAdd(&g_acc, (double)s);
    }
}

__global__ void ssim_finalize_kernel(float* __restrict__ out) {
    out[0] = (float)(g_acc / ((double)NIMG * IMG * IMG));
}

extern "C" void kernel_launch(void* const* d_in, const int* in_sizes, int n_in,
                              void* d_out, int out_size)
{
    const float* x = (const float*)d_in[0];
    const float* y = (const float*)d_in[1];
    const float* w = (const float*)d_in[2];
    float* out = (float*)d_out;

    ssim_zero_kernel<<<1, 1>>>();
    dim3 grid(IMG / TILE, IMG / TILE, NIMG);   // 16 x 16 x 32 = 8192 CTAs
    ssim_main_kernel<<<grid, NTHREADS>>>(x, y, w);
    ssim_finalize_kernel<<<1, 1>>>(out);
}

// round 3
// speedup vs baseline: 1.5208x; 1.3868x over previous
#include <cuda_runtime.h>

#define IMG     512
#define NIMG    32
#define WIN     11
#define TILE_W  32
#define TILE_H  54
#define INH     (TILE_H + WIN - 1)   // 64 haloed rows
#define HROWS   (INH + 2)            // 66: +2 pad rows for tail-segment overrun
#define HSTRIDE 33                   // odd u64 stride: 2-way max conflicts
#define NTHREADS 256

typedef unsigned long long u64;

__device__ double g_acc;

__device__ __forceinline__ u64 pack2(float a, float b) {
    u64 r; asm("mov.b64 %0, {%1,%2};" : "=l"(r) : "f"(a), "f"(b)); return r;
}
__device__ __forceinline__ void unpack2(u64 v, float &a, float &b) {
    asm("mov.b64 {%0,%1}, %2;" : "=f"(a), "=f"(b) : "l"(v));
}
__device__ __forceinline__ u64 fma2(u64 a, u64 b, u64 c) {
    u64 d; asm("fma.rn.f32x2 %0, %1, %2, %3;" : "=l"(d) : "l"(a), "l"(b), "l"(c)); return d;
}
__device__ __forceinline__ u64 mul2(u64 a, u64 b) {
    u64 d; asm("mul.rn.f32x2 %0, %1, %2;" : "=l"(d) : "l"(a), "l"(b)); return d;
}

__global__ void ssim_zero_kernel() { g_acc = 0.0; }

__global__ void __launch_bounds__(NTHREADS)
ssim_main_kernel(const float* __restrict__ x,
                 const float* __restrict__ y,
                 const float* __restrict__ w)
{
    __shared__ float g[WIN];
    __shared__ u64   hmu[HROWS * HSTRIDE];   // h-conv packed {mu_s, mu_d}
    __shared__ u64   hsq[HROWS * HSTRIDE];   // h-conv packed {E[s2], E[d2]}
    __shared__ float warpsum[NTHREADS / 32];

    const int tid = threadIdx.x;

    // Separable taps: g[i] = sum_j w[i][j] (exact: sum over full window = 1)
    if (tid < WIN) {
        float s = 0.f;
        #pragma unroll
        for (int j = 0; j < WIN; j++) s += w[tid * WIN + j];
        g[tid] = s;
    }
    __syncthreads();

    float garr[WIN];
    u64   gg[WIN];
    #pragma unroll
    for (int k = 0; k < WIN; k++) {
        garr[k] = g[k];
        gg[k]   = pack2(garr[k], garr[k]);
    }

    const int n      = blockIdx.z;
    const int tile_x = blockIdx.x * TILE_W;
    const int tile_y = blockIdx.y * TILE_H;
    const float* __restrict__ xb = x + (size_t)n * IMG * IMG;
    const float* __restrict__ yb = y + (size_t)n * IMG * IMG;

    // ---- Stage B: horizontal pass, 64 rows x 4 segments of 8 = 256 threads.
    // Each thread streams 18 input pixels straight from global (L1), rolls 8 outputs.
    {
        const int row = tid >> 2;             // 0..63 (haloed row)
        const int s0  = (tid & 3) * 8;        // output segment start (0,8,16,24)
        const int gr  = tile_y + row - WIN / 2;
        const int gc0 = tile_x + s0 - WIN / 2;

        u64 amu[8], asq[8];
        #pragma unroll
        for (int o = 0; o < 8; o++) { amu[o] = 0ull; asq[o] = 0ull; }

        if ((unsigned)gr < IMG) {
            const float* __restrict__ xr = xb + gr * IMG;
            const float* __restrict__ yr = yb + gr * IMG;
            if (gc0 >= 0 && gc0 + 17 < IMG) {
                // interior fast path: no column predication
                #pragma unroll
                for (int i = 0; i < 18; i++) {
                    const float vx = xr[gc0 + i];
                    const float vy = yr[gc0 + i];
                    const u64 p  = pack2(vx + vy, vx - vy);
                    const u64 p2 = mul2(p, p);
                    #pragma unroll
                    for (int o = 0; o < 8; o++) {
                        const int k = i - o;
                        if (k >= 0 && k < WIN) {
                            amu[o] = fma2(gg[k], p,  amu[o]);
                            asq[o] = fma2(gg[k], p2, asq[o]);
                        }
                    }
                }
            } else {
                #pragma unroll
                for (int i = 0; i < 18; i++) {
                    const int gc = gc0 + i;
                    float vx = 0.f, vy = 0.f;
                    if ((unsigned)gc < IMG) { vx = xr[gc]; vy = yr[gc]; }
                    const u64 p  = pack2(vx + vy, vx - vy);
                    const u64 p2 = mul2(p, p);
                    #pragma unroll
                    for (int o = 0; o < 8; o++) {
                        const int k = i - o;
                        if (k >= 0 && k < WIN) {
                            amu[o] = fma2(gg[k], p,  amu[o]);
                            asq[o] = fma2(gg[k], p2, asq[o]);
                        }
                    }
                }
            }
        }
        #pragma unroll
        for (int o = 0; o < 8; o++) {
            hmu[row * HSTRIDE + s0 + o] = amu[o];
            hsq[row * HSTRIDE + s0 + o] = asq[o];
        }
    }
    __syncthreads();

    // ---- Stage C: vertical pass + SSIM. 7 segments x 32 cols = 224 threads.
    const float C1  = 1e-4f;
    const float C2  = 9e-4f;
    const float EPS = 1e-8f;

    float local = 0.f;
    {
        const int col = tid & 31;
        const int seg = tid >> 5;             // 0..7; seg 7 idle
        if (seg < 7) {
            const int r0   = seg * 8;
            const int nout = (seg == 6) ? 6 : 8;   // 6*8+6 = 54 rows

            u64 vmu[8], vsq[8];
            #pragma unroll
            for (int o = 0; o < 8; o++) { vmu[o] = 0ull; vsq[o] = 0ull; }

            #pragma unroll
            for (int i = 0; i < 18; i++) {
                const u64 m = hmu[(r0 + i) * HSTRIDE + col];  // rows up to 65: pad ok
                const u64 q = hsq[(r0 + i) * HSTRIDE + col];
                #pragma unroll
                for (int o = 0; o < 8; o++) {
                    const int k = i - o;
                    if (k >= 0 && k < WIN) {
                        vmu[o] = fma2(gg[k], m, vmu[o]);
                        vsq[o] = fma2(gg[k], q, vsq[o]);
                    }
                }
            }

            #pragma unroll
            for (int o = 0; o < 8; o++) {
                const int orow = r0 + o;
                if (o < nout && (tile_y + orow) < IMG) {
                    float a, b, e, f;
                    const u64 q2 = mul2(vmu[o], vmu[o]);   // {mu_s^2, mu_d^2}
                    unpack2(q2, a, b);
                    unpack2(vsq[o], e, f);                 // {E[s2], E[d2]}
                    const float P  = 0.5f * (a - b);       // 2*mu_x*mu_y
                    const float Qm = 0.5f * (a + b);       // mu_x^2 + mu_y^2
                    const float R  = 0.5f * (e - f) - P;   // 2*sig_xy
                    const float S  = 0.5f * (e + f) - Qm;  // sig_x^2 + sig_y^2
                    const float num = (P + C1) * (R + C2);
                    const float den = (Qm + C1) * (S + C2);
                    float v = __fdividef(num, den + EPS);
                    v = fminf(fmaxf(v, 0.f), 1.f);
                    local += v;
                }
            }
        }
    }

    // ---- Block reduction
    #pragma unroll
    for (int off = 16; off; off >>= 1)
        local += __shfl_down_sync(0xffffffffu, local, off);
    if ((tid & 31) == 0) warpsum[tid >> 5] = local;
    __syncthreads();
    if (tid == 0) {
        float s = 0.f;
        #pragma unroll
        for (int i = 0; i < NTHREADS / 32; i++) s += warpsum[i];
        atomicAdd(&g_acc, (double)s);
    }
}

__global__ void ssim_finalize_kernel(float* __restrict__ out) {
    out[0] = (float)(g_acc / ((double)NIMG * IMG * IMG));
}

extern "C" void kernel_launch(void* const* d_in, const int* in_sizes, int n_in,
                              void* d_out, int out_size)
{
    const float* x = (const float*)d_in[0];
    const float* y = (const float*)d_in[1];
    const float* w = (const float*)d_in[2];
    float* out = (float*)d_out;

    ssim_zero_kernel<<<1, 1>>>();
    dim3 grid(IMG / TILE_W, (IMG + TILE_H - 1) / TILE_H, NIMG);  // 16 x 10 x 32
    ssim_main_kernel<<<grid, NTHREADS>>>(x, y, w);
    ssim_finalize_kernel<<<1, 1>>>(out);
}

// round 4
// speedup vs baseline: 1.9867x; 1.3064x over previous
#include <cuda_runtime.h>

#define IMG     512
#define NIMG    32
#define WIN     11
#define TILE_W  32
#define TILE_H  54
#define INH     (TILE_H + WIN - 1)   // 64 haloed rows
#define HROWS   (INH + 2)            // 66: +2 pad rows for tail-segment overrun
#define HSTRIDE 34                   // even u64 stride: 16B-aligned row starts
#define NTHREADS 256

typedef unsigned long long u64;

__device__ double g_acc;

__device__ __forceinline__ u64 pack2(float a, float b) {
    u64 r; asm("mov.b64 %0, {%1,%2};" : "=l"(r) : "f"(a), "f"(b)); return r;
}
__device__ __forceinline__ void unpack2(u64 v, float &a, float &b) {
    asm("mov.b64 {%0,%1}, %2;" : "=f"(a), "=f"(b) : "l"(v));
}
__device__ __forceinline__ u64 fma2(u64 a, u64 b, u64 c) {
    u64 d; asm("fma.rn.f32x2 %0, %1, %2, %3;" : "=l"(d) : "l"(a), "l"(b), "l"(c)); return d;
}
__device__ __forceinline__ u64 mul2(u64 a, u64 b) {
    u64 d; asm("mul.rn.f32x2 %0, %1, %2;" : "=l"(d) : "l"(a), "l"(b)); return d;
}

__global__ void ssim_zero_kernel() { g_acc = 0.0; }

__global__ void __launch_bounds__(NTHREADS, 2)
ssim_main_kernel(const float* __restrict__ x,
                 const float* __restrict__ y,
                 const float* __restrict__ w)
{
    __shared__ float g[WIN];
    __shared__ u64   hmu[HROWS * HSTRIDE];   // h-conv packed {mu_s, mu_d}
    __shared__ u64   hsq[HROWS * HSTRIDE];   // h-conv packed {E[s2], E[d2]}
    __shared__ float warpsum[NTHREADS / 32];

    const int tid = threadIdx.x;

    // Separable taps: g[i] = sum_j w[i][j] (exact: rows of outer(g,g) with sum(g)=1)
    if (tid < WIN) {
        float s = 0.f;
        #pragma unroll
        for (int j = 0; j < WIN; j++) s += w[tid * WIN + j];
        g[tid] = s;
    }
    __syncthreads();

    // Symmetric taps: g[k] == g[10-k] bit-exact -> keep only 6 packed regs.
    u64 gg[6];
    #pragma unroll
    for (int k = 0; k < 6; k++) gg[k] = pack2(g[k], g[k]);
#define GG(k) gg[(k) < 6 ? (k) : 10 - (k)]

    const int n      = blockIdx.z;
    const int tile_x = blockIdx.x * TILE_W;
    const int tile_y = blockIdx.y * TILE_H;
    const float* __restrict__ xb = x + (size_t)n * IMG * IMG;
    const float* __restrict__ yb = y + (size_t)n * IMG * IMG;

    // ---- Stage B: horizontal pass, 64 rows x 4 segments of 8 = 256 threads.
    {
        const int row = tid >> 2;             // 0..63 (haloed row)
        const int s0  = (tid & 3) * 8;        // output segment start (0,8,16,24)
        const int gr  = tile_y + row - WIN / 2;
        const int gc0 = tile_x + s0 - WIN / 2;   // first needed input col
        const int gcr = tile_x + s0 - 8;         // 8-aligned vector base (= gc0-3)

        u64 amu[8], asq[8];
        #pragma unroll
        for (int o = 0; o < 8; o++) { amu[o] = 0ull; asq[o] = 0ull; }

        if ((unsigned)gr < IMG) {
            const float* __restrict__ xr = xb + gr * IMG;
            const float* __restrict__ yr = yb + gr * IMG;
            if (gcr >= 0 && gcr + 23 < IMG) {
                // interior fast path: 6+6 LDG.128, stream elements t=0..17
                const float4* __restrict__ xr4 = (const float4*)(xr + gcr);
                const float4* __restrict__ yr4 = (const float4*)(yr + gcr);
                #pragma unroll
                for (int q = 0; q < 6; q++) {
                    const float4 xv = xr4[q];
                    const float4 yv = yr4[q];
                    const float xe[4] = {xv.x, xv.y, xv.z, xv.w};
                    const float ye[4] = {yv.x, yv.y, yv.z, yv.w};
                    #pragma unroll
                    for (int e = 0; e < 4; e++) {
                        const int t = 4 * q + e - 3;   // input index in 18-window
                        if (t < 0 || t > 17) continue;
                        const u64 p  = pack2(xe[e] + ye[e], xe[e] - ye[e]);
                        const u64 p2 = mul2(p, p);
                        #pragma unroll
                        for (int o = 0; o < 8; o++) {
                            const int k = t - o;
                            if (k >= 0 && k < WIN) {
                                amu[o] = fma2(GG(k), p,  amu[o]);
                                asq[o] = fma2(GG(k), p2, asq[o]);
                            }
                        }
                    }
                }
            } else {
                #pragma unroll
                for (int t = 0; t < 18; t++) {
                    const int gc = gc0 + t;
                    float vx = 0.f, vy = 0.f;
                    if ((unsigned)gc < IMG) { vx = xr[gc]; vy = yr[gc]; }
                    const u64 p  = pack2(vx + vy, vx - vy);
                    const u64 p2 = mul2(p, p);
                    #pragma unroll
                    for (int o = 0; o < 8; o++) {
                        const int k = t - o;
                        if (k >= 0 && k < WIN) {
                            amu[o] = fma2(GG(k), p,  amu[o]);
                            asq[o] = fma2(GG(k), p2, asq[o]);
                        }
                    }
                }
            }
        }
        // STS.128 pairs: (row*34 + s0 + even) is even -> 16B aligned
        #pragma unroll
        for (int o = 0; o < 8; o += 2) {
            *(ulonglong2*)&hmu[row * HSTRIDE + s0 + o] = make_ulonglong2(amu[o], amu[o + 1]);
            *(ulonglong2*)&hsq[row * HSTRIDE + s0 + o] = make_ulonglong2(asq[o], asq[o + 1]);
        }
        // zero the 2 pad rows (64,65) read by the tail segment
        if (tid < 2 * HSTRIDE) {
            hmu[INH * HSTRIDE + tid] = 0ull;
            hsq[INH * HSTRIDE + tid] = 0ull;
        }
    }
    __syncthreads();

    // ---- Stage C: vertical pass + SSIM. 7 segments x 32 cols = 224 threads.
    const float C1  = 1e-4f;
    const float C2  = 9e-4f;
    const float EPS = 1e-8f;

    float local = 0.f;
    {
        const int col = tid & 31;
        const int seg = tid >> 5;             // 0..7; seg 7 idle
        if (seg < 7) {
            const int r0   = seg * 8;
            const int nout = (seg == 6) ? 6 : 8;   // 6*8+6 = 54 rows

            u64 vmu[8], vsq[8];
            #pragma unroll
            for (int o = 0; o < 8; o++) { vmu[o] = 0ull; vsq[o] = 0ull; }

            #pragma unroll
            for (int i = 0; i < 18; i++) {
                const u64 m = hmu[(r0 + i) * HSTRIDE + col];
                const u64 q = hsq[(r0 + i) * HSTRIDE + col];
                #pragma unroll
                for (int o = 0; o < 8; o++) {
                    const int k = i - o;
                    if (k >= 0 && k < WIN) {
                        vmu[o] = fma2(GG(k), m, vmu[o]);
                        vsq[o] = fma2(GG(k), q, vsq[o]);
                    }
                }
            }

            #pragma unroll
            for (int o = 0; o < 8; o++) {
                const int orow = r0 + o;
                if (o < nout && (tile_y + orow) < IMG) {
                    float a, b, e, f;
                    const u64 q2 = mul2(vmu[o], vmu[o]);   // {mu_s^2, mu_d^2}
                    unpack2(q2, a, b);
                    unpack2(vsq[o], e, f);                 // {E[s2], E[d2]}
                    const float P  = 0.5f * (a - b);       // 2*mu_x*mu_y
                    const float Qm = 0.5f * (a + b);       // mu_x^2 + mu_y^2
                    const float R  = 0.5f * (e - f) - P;   // 2*sig_xy
                    const float S  = 0.5f * (e + f) - Qm;  // sig_x^2 + sig_y^2
                    const float num = (P + C1) * (R + C2);
                    const float den = (Qm + C1) * (S + C2);
                    float v = __fdividef(num, den + EPS);
                    v = fminf(fmaxf(v, 0.f), 1.f);
                    local += v;
                }
            }
        }
    }

    // ---- Block reduction
    #pragma unroll
    for (int off = 16; off; off >>= 1)
        local += __shfl_down_sync(0xffffffffu, local, off);
    if ((tid & 31) == 0) warpsum[tid >> 5] = local;
    __syncthreads();
    if (tid == 0) {
        float s = 0.f;
        #pragma unroll
        for (int i = 0; i < NTHREADS / 32; i++) s += warpsum[i];
        atomicAdd(&g_acc, (double)s);
    }
}

__global__ void ssim_finalize_kernel(float* __restrict__ out) {
    out[0] = (float)(g_acc / ((double)NIMG * IMG * IMG));
}

extern "C" void kernel_launch(void* const* d_in, const int* in_sizes, int n_in,
                              void* d_out, int out_size)
{
    const float* x = (const float*)d_in[0];
    const float* y = (const float*)d_in[1];
    const float* w = (const float*)d_in[2];
    float* out = (float*)d_out;

    ssim_zero_kernel<<<1, 1>>>();
    dim3 grid(IMG / TILE_W, (IMG + TILE_H - 1) / TILE_H, NIMG);  // 16 x 10 x 32
    ssim_main_kernel<<<grid, NTHREADS>>>(x, y, w);
    ssim_finalize_kernel<<<1, 1>>>(out);
}

// round 5
// speedup vs baseline: 2.1318x; 1.0731x over previous
#include <cuda_runtime.h>

#define IMG     512
#define NIMG    32
#define WIN     11
#define TILE_W  32
#define TILE_H  64
#define INH     (TILE_H + WIN - 1)   // 74 haloed rows
#define HROWS   (INH + 2)            // 76: +2 pad rows for tail-segment overrun
#define HSTRIDE 34                   // even u64 stride: 16B-aligned row starts
#define NTHREADS 256
#define HTASKS  (INH * 4)            // 296 h-pass tasks (row, 8-col segment)

typedef unsigned long long u64;

__device__ double g_acc;

__device__ __forceinline__ u64 pack2(float a, float b) {
    u64 r; asm("mov.b64 %0, {%1,%2};" : "=l"(r) : "f"(a), "f"(b)); return r;
}
__device__ __forceinline__ void unpack2(u64 v, float &a, float &b) {
    asm("mov.b64 {%0,%1}, %2;" : "=f"(a), "=f"(b) : "l"(v));
}
__device__ __forceinline__ u64 fma2(u64 a, u64 b, u64 c) {
    u64 d; asm("fma.rn.f32x2 %0, %1, %2, %3;" : "=l"(d) : "l"(a), "l"(b), "l"(c)); return d;
}
__device__ __forceinline__ u64 mul2(u64 a, u64 b) {
    u64 d; asm("mul.rn.f32x2 %0, %1, %2;" : "=l"(d) : "l"(a), "l"(b)); return d;
}

__global__ void ssim_zero_kernel() { g_acc = 0.0; }

__global__ void __launch_bounds__(NTHREADS, 3)
ssim_main_kernel(const float* __restrict__ x,
                 const float* __restrict__ y,
                 const float* __restrict__ w)
{
    __shared__ float g[WIN];
    __shared__ u64   hmu[HROWS * HSTRIDE];   // h-conv packed {mu_s, mu_d}
    __shared__ u64   hsq[HROWS * HSTRIDE];   // h-conv packed {E[s2], E[d2]}
    __shared__ float warpsum[NTHREADS / 32];

    const int tid = threadIdx.x;

    // Separable taps: g[i] = sum_j w[i][j] (exact: rows of outer(g,g), sum(g)=1)
    if (tid < WIN) {
        float s = 0.f;
        #pragma unroll
        for (int j = 0; j < WIN; j++) s += w[tid * WIN + j];
        g[tid] = s;
    }
    // zero the 2 pad rows (74,75) read by the tail v-segment
    if (tid < 2 * HSTRIDE) {
        hmu[INH * HSTRIDE + tid] = 0ull;
        hsq[INH * HSTRIDE + tid] = 0ull;
    }
    __syncthreads();

    // Symmetric taps: g[k] == g[10-k] bit-exact -> keep only 6 packed regs.
    u64 gg[6];
    #pragma unroll
    for (int k = 0; k < 6; k++) gg[k] = pack2(g[k], g[k]);
#define GG(k) gg[(k) < 6 ? (k) : 10 - (k)]

    const int n      = blockIdx.z;
    const int tile_x = blockIdx.x * TILE_W;
    const int tile_y = blockIdx.y * TILE_H;
    const float* __restrict__ xb = x + (size_t)n * IMG * IMG;
    const float* __restrict__ yb = y + (size_t)n * IMG * IMG;

    // ---- Stage B: horizontal pass. 296 tasks (74 rows x 4 segments of 8 outputs),
    // strided over 256 threads. Inputs stream straight from global (L1).
    for (int task = tid; task < HTASKS; task += NTHREADS) {
        const int row = task >> 2;               // 0..73 (haloed row)
        const int s0  = (task & 3) * 8;          // output segment start
        const int gr  = tile_y + row - WIN / 2;
        const int gc0 = tile_x + s0 - WIN / 2;   // first needed input col
        const int gcr = tile_x + s0 - 8;         // 8-aligned vector base (= gc0-3)

        u64 amu[8], asq[8];
        #pragma unroll
        for (int o = 0; o < 8; o++) { amu[o] = 0ull; asq[o] = 0ull; }

        if ((unsigned)gr < IMG) {
            const float* __restrict__ xr = xb + gr * IMG;
            const float* __restrict__ yr = yb + gr * IMG;
            if (gcr >= 0 && gcr + 23 < IMG) {
                const float4* __restrict__ xr4 = (const float4*)(xr + gcr);
                const float4* __restrict__ yr4 = (const float4*)(yr + gcr);
                #pragma unroll
                for (int q = 0; q < 6; q++) {
                    const float4 xv = xr4[q];
                    const float4 yv = yr4[q];
                    const float xe[4] = {xv.x, xv.y, xv.z, xv.w};
                    const float ye[4] = {yv.x, yv.y, yv.z, yv.w};
                    #pragma unroll
                    for (int e = 0; e < 4; e++) {
                        const int t = 4 * q + e - 3;   // input index in 18-window
                        if (t < 0 || t > 17) continue;
                        const u64 p  = pack2(xe[e] + ye[e], xe[e] - ye[e]);
                        const u64 p2 = mul2(p, p);
                        #pragma unroll
                        for (int o = 0; o < 8; o++) {
                            const int k = t - o;
                            if (k >= 0 && k < WIN) {
                                amu[o] = fma2(GG(k), p,  amu[o]);
                                asq[o] = fma2(GG(k), p2, asq[o]);
                            }
                        }
                    }
                }
            } else {
                #pragma unroll
                for (int t = 0; t < 18; t++) {
                    const int gc = gc0 + t;
                    float vx = 0.f, vy = 0.f;
                    if ((unsigned)gc < IMG) { vx = xr[gc]; vy = yr[gc]; }
                    const u64 p  = pack2(vx + vy, vx - vy);
                    const u64 p2 = mul2(p, p);
                    #pragma unroll
                    for (int o = 0; o < 8; o++) {
                        const int k = t - o;
                        if (k >= 0 && k < WIN) {
                            amu[o] = fma2(GG(k), p,  amu[o]);
                            asq[o] = fma2(GG(k), p2, asq[o]);
                        }
                    }
                }
            }
        }
        #pragma unroll
        for (int o = 0; o < 8; o += 2) {
            *(ulonglong2*)&hmu[row * HSTRIDE + s0 + o] = make_ulonglong2(amu[o], amu[o + 1]);
            *(ulonglong2*)&hsq[row * HSTRIDE + s0 + o] = make_ulonglong2(asq[o], asq[o + 1]);
        }
    }
    __syncthreads();

    // ---- Stage C: vertical pass + SSIM. 8 segments x 8 rows x 32 cols = 256 threads (full).
    const float C1  = 1e-4f;
    const float C2  = 9e-4f;
    const float EPS = 1e-8f;

    float local = 0.f;
    {
        const int col = tid & 31;
        const int r0  = (tid >> 5) * 8;          // 0,8,...,56

        u64 vmu[8], vsq[8];
        #pragma unroll
        for (int o = 0; o < 8; o++) { vmu[o] = 0ull; vsq[o] = 0ull; }

        #pragma unroll
        for (int i = 0; i < 18; i++) {
            const u64 m = hmu[(r0 + i) * HSTRIDE + col];
            const u64 q = hsq[(r0 + i) * HSTRIDE + col];
            #pragma unroll
            for (int o = 0; o < 8; o++) {
                const int k = i - o;
                if (k >= 0 && k < WIN) {
                    vmu[o] = fma2(GG(k), m, vmu[o]);
                    vsq[o] = fma2(GG(k), q, vsq[o]);
                }
            }
        }

        #pragma unroll
        for (int o = 0; o < 8; o++) {
            // tile grid is exact (512 = 8*64), rows always in range
            float a, b, e, f;
            const u64 q2 = mul2(vmu[o], vmu[o]);   // {mu_s^2, mu_d^2}
            unpack2(q2, a, b);
            unpack2(vsq[o], e, f);                 // {E[s2], E[d2]}
            const float P  = 0.5f * (a - b);       // 2*mu_x*mu_y
            const float Qm = 0.5f * (a + b);       // mu_x^2 + mu_y^2
            const float R  = 0.5f * (e - f) - P;   // 2*sig_xy
            const float S  = 0.5f * (e + f) - Qm;  // sig_x^2 + sig_y^2
            const float num = (P + C1) * (R + C2);
            const float den = (Qm + C1) * (S + C2);
            float v = __fdividef(num, den + EPS);
            v = fminf(fmaxf(v, 0.f), 1.f);
            local += v;
        }
    }

    // ---- Block reduction
    #pragma unroll
    for (int off = 16; off; off >>= 1)
        local += __shfl_down_sync(0xffffffffu, local, off);
    if ((tid & 31) == 0) warpsum[tid >> 5] = local;
    __syncthreads();
    if (tid == 0) {
        float s = 0.f;
        #pragma unroll
        for (int i = 0; i < NTHREADS / 32; i++) s += warpsum[i];
        atomicAdd(&g_acc, (double)s);
    }
}

__global__ void ssim_finalize_kernel(float* __restrict__ out) {
    out[0] = (float)(g_acc / ((double)NIMG * IMG * IMG));
}

extern "C" void kernel_launch(void* const* d_in, const int* in_sizes, int n_in,
                              void* d_out, int out_size)
{
    const float* x = (const float*)d_in[0];
    const float* y = (const float*)d_in[1];
    const float* w = (const float*)d_in[2];
    float* out = (float*)d_out;

    ssim_zero_kernel<<<1, 1>>>();
    dim3 grid(IMG / TILE_W, IMG / TILE_H, NIMG);   // 16 x 8 x 32 = 4096 CTAs
    ssim_main_kernel<<<grid, NTHREADS>>>(x, y, w);
    ssim_finalize_kernel<<<1, 1>>>(out);
}

// round 6
// speedup vs baseline: 2.1690x; 1.0174x over previous
#include <cuda_runtime.h>

#define IMG     512
#define NIMG    32
#define WIN     11
#define TILE_W  32
#define TILE_H  64
#define INH     (TILE_H + WIN - 1)   // 74 haloed rows
#define HSTRIDE 34                   // even u64 stride: 16B-aligned row starts
#define NTHREADS 256
#define HTASKS  (INH * 4)            // 296 h-pass tasks (row, 8-col segment)
#define NBLOCKS (16 * 8 * 32)        // 4096 CTAs

typedef unsigned long long u64;

__device__ double       g_acc   = 0.0;
__device__ unsigned int g_count = 0u;

__device__ __forceinline__ u64 pack2(float a, float b) {
    u64 r; asm("mov.b64 %0, {%1,%2};" : "=l"(r) : "f"(a), "f"(b)); return r;
}
__device__ __forceinline__ void unpack2(u64 v, float &a, float &b) {
    asm("mov.b64 {%0,%1}, %2;" : "=f"(a), "=f"(b) : "l"(v));
}
__device__ __forceinline__ u64 fma2(u64 a, u64 b, u64 c) {
    u64 d; asm("fma.rn.f32x2 %0, %1, %2, %3;" : "=l"(d) : "l"(a), "l"(b), "l"(c)); return d;
}
__device__ __forceinline__ u64 mul2(u64 a, u64 b) {
    u64 d; asm("mul.rn.f32x2 %0, %1, %2;" : "=l"(d) : "l"(a), "l"(b)); return d;
}

// Normalized 1D Gaussian taps, win=11, sigma=1.5 (standard SSIM window, symmetric).
#define G0 0.00102838f
#define G1 0.00759876f
#define G2 0.03600077f
#define G3 0.10936069f
#define G4 0.21300553f
#define G5 0.26601172f

__global__ void __launch_bounds__(NTHREADS, 3)
ssim_main_kernel(const float* __restrict__ x,
                 const float* __restrict__ y,
                 float* __restrict__ out)
{
    __shared__ u64   hmu[INH * HSTRIDE];   // h-conv packed {mu_s, mu_d}
    __shared__ u64   hsq[INH * HSTRIDE];   // h-conv packed {E[s2], E[d2]}
    __shared__ float warpsum[NTHREADS / 32];

    const int tid = threadIdx.x;

    const u64 gg[6] = { pack2(G0,G0), pack2(G1,G1), pack2(G2,G2),
                        pack2(G3,G3), pack2(G4,G4), pack2(G5,G5) };
#define GG(k) gg[(k) < 6 ? (k) : 10 - (k)]

    const int n      = blockIdx.z;
    const int tile_x = blockIdx.x * TILE_W;
    const int tile_y = blockIdx.y * TILE_H;
    const float* __restrict__ xb = x + (size_t)n * IMG * IMG;
    const float* __restrict__ yb = y + (size_t)n * IMG * IMG;

    // ---- Stage B: horizontal pass. 296 tasks (74 rows x 4 segments of 8 outputs),
    // strided over 256 threads. Inputs stream straight from global (L1).
    for (int task = tid; task < HTASKS; task += NTHREADS) {
        const int row = task >> 2;               // 0..73 (haloed row)
        const int s0  = (task & 3) * 8;          // output segment start
        const int gr  = tile_y + row - WIN / 2;
        const int gc0 = tile_x + s0 - WIN / 2;   // first needed input col
        const int gcr = tile_x + s0 - 8;         // 8-aligned vector base (= gc0-3)

        u64 amu[8], asq[8];
        #pragma unroll
        for (int o = 0; o < 8; o++) { amu[o] = 0ull; asq[o] = 0ull; }

        if ((unsigned)gr < IMG) {
            const float* __restrict__ xr = xb + gr * IMG;
            const float* __restrict__ yr = yb + gr * IMG;
            if (gcr >= 0 && gcr + 23 < IMG) {
                const float4* __restrict__ xr4 = (const float4*)(xr + gcr);
                const float4* __restrict__ yr4 = (const float4*)(yr + gcr);
                #pragma unroll
                for (int q = 0; q < 6; q++) {
                    const float4 xv = xr4[q];
                    const float4 yv = yr4[q];
                    const float xe[4] = {xv.x, xv.y, xv.z, xv.w};
                    const float ye[4] = {yv.x, yv.y, yv.z, yv.w};
                    #pragma unroll
                    for (int e = 0; e < 4; e++) {
                        const int t = 4 * q + e - 3;   // input index in 18-window
                        if (t < 0 || t > 17) continue;
                        const u64 p  = pack2(xe[e] + ye[e], xe[e] - ye[e]);
                        const u64 p2 = mul2(p, p);
                        #pragma unroll
                        for (int o = 0; o < 8; o++) {
                            const int k = t - o;
                            if (k >= 0 && k < WIN) {
                                amu[o] = fma2(GG(k), p,  amu[o]);
                                asq[o] = fma2(GG(k), p2, asq[o]);
                            }
                        }
                    }
                }
            } else {
                #pragma unroll
                for (int t = 0; t < 18; t++) {
                    const int gc = gc0 + t;
                    float vx = 0.f, vy = 0.f;
                    if ((unsigned)gc < IMG) { vx = xr[gc]; vy = yr[gc]; }
                    const u64 p  = pack2(vx + vy, vx - vy);
                    const u64 p2 = mul2(p, p);
                    #pragma unroll
                    for (int o = 0; o < 8; o++) {
                        const int k = t - o;
                        if (k >= 0 && k < WIN) {
                            amu[o] = fma2(GG(k), p,  amu[o]);
                            asq[o] = fma2(GG(k), p2, asq[o]);
                        }
                    }
                }
            }
        }
        #pragma unroll
        for (int o = 0; o < 8; o += 2) {
            *(ulonglong2*)&hmu[row * HSTRIDE + s0 + o] = make_ulonglong2(amu[o], amu[o + 1]);
            *(ulonglong2*)&hsq[row * HSTRIDE + s0 + o] = make_ulonglong2(asq[o], asq[o + 1]);
        }
    }
    __syncthreads();

    // ---- Stage C: vertical pass + SSIM. 8 segments x 8 rows x 32 cols = 256 threads.
    const float C1  = 1e-4f;
    const float C2  = 9e-4f;
    const float EPS = 1e-8f;

    float local = 0.f;
    {
        const int col = tid & 31;
        const int r0  = (tid >> 5) * 8;          // 0,8,...,56 ; reads rows r0..r0+17 <= 73

        u64 vmu[8], vsq[8];
        #pragma unroll
        for (int o = 0; o < 8; o++) { vmu[o] = 0ull; vsq[o] = 0ull; }

        #pragma unroll
        for (int i = 0; i < 18; i++) {
            const u64 m = hmu[(r0 + i) * HSTRIDE + col];
            const u64 q = hsq[(r0 + i) * HSTRIDE + col];
            #pragma unroll
            for (int o = 0; o < 8; o++) {
                const int k = i - o;
                if (k >= 0 && k < WIN) {
                    vmu[o] = fma2(GG(k), m, vmu[o]);
                    vsq[o] = fma2(GG(k), q, vsq[o]);
                }
            }
        }

        #pragma unroll
        for (int o = 0; o < 8; o++) {
            float a, b, e, f;
            const u64 q2 = mul2(vmu[o], vmu[o]);   // {mu_s^2, mu_d^2}
            unpack2(q2, a, b);
            unpack2(vsq[o], e, f);                 // {E[s2], E[d2]}
            const float P  = 0.5f * (a - b);       // 2*mu_x*mu_y
            const float Qm = 0.5f * (a + b);       // mu_x^2 + mu_y^2
            const float R  = 0.5f * (e - f) - P;   // 2*sig_xy
            const float S  = 0.5f * (e + f) - Qm;  // sig_x^2 + sig_y^2
            const float num = (P + C1) * (R + C2);
            const float den = (Qm + C1) * (S + C2);
            float v = __fdividef(num, den + EPS);
            v = fminf(fmaxf(v, 0.f), 1.f);
            local += v;
        }
    }

    // ---- Block reduction
    #pragma unroll
    for (int off = 16; off; off >>= 1)
        local += __shfl_down_sync(0xffffffffu, local, off);
    if ((tid & 31) == 0) warpsum[tid >> 5] = local;
    __syncthreads();

    // ---- Fused finale: self-resetting device accumulator, last CTA writes out.
    if (tid == 0) {
        float s = 0.f;
        #pragma unroll
        for (int i = 0; i < NTHREADS / 32; i++) s += warpsum[i];
        atomicAdd(&g_acc, (double)s);
        __threadfence();
        const unsigned done = atomicAdd(&g_count, 1u);
        if (done == NBLOCKS - 1) {
            __threadfence();
            const double v = *(volatile double*)&g_acc;
            out[0] = (float)(v / ((double)NIMG * IMG * IMG));
            *(volatile double*)&g_acc = 0.0;            // reset for next replay
            __threadfence();
            *(volatile unsigned*)&g_count = 0u;
        }
    }
}

extern "C" void kernel_launch(void* const* d_in, const int* in_sizes, int n_in,
                              void* d_out, int out_size)
{
    const float* x = (const float*)d_in[0];
    const float* y = (const float*)d_in[1];
    float* out = (float*)d_out;

    dim3 grid(IMG / TILE_W, IMG / TILE_H, NIMG);   // 16 x 8 x 32 = 4096 CTAs
    ssim_main_kernel<<<grid, NTHREADS>>>(x, y, out);
}

// round 7
// speedup vs baseline: 2.3113x; 1.0656x over previous
#include <cuda_runtime.h>

#define IMG     512
#define NIMG    32
#define WIN     11
#define TILE_W  32
#define TILE_H  54
#define INH     (TILE_H + WIN - 1)   // 64 haloed rows (exactly 256 h-tasks)
#define HROWS   (INH + 1)            // +1 zero pad row for uniform 17-row v-unroll
#define HSTRIDE 34                   // even u64 stride: 16B-aligned row starts
#define NTHREADS 256
#define GRID_Y  ((IMG + TILE_H - 1) / TILE_H)     // 10
#define NBLOCKS (16 * GRID_Y * 32)                // 5120 CTAs

typedef unsigned long long u64;

__device__ double       g_acc   = 0.0;
__device__ unsigned int g_count = 0u;

__device__ __forceinline__ u64 pack2(float a, float b) {
    u64 r; asm("mov.b64 %0, {%1,%2};" : "=l"(r) : "f"(a), "f"(b)); return r;
}
__device__ __forceinline__ void unpack2(u64 v, float &a, float &b) {
    asm("mov.b64 {%0,%1}, %2;" : "=f"(a), "=f"(b) : "l"(v));
}
__device__ __forceinline__ u64 fma2(u64 a, u64 b, u64 c) {
    u64 d; asm("fma.rn.f32x2 %0, %1, %2, %3;" : "=l"(d) : "l"(a), "l"(b), "l"(c)); return d;
}
__device__ __forceinline__ u64 mul2(u64 a, u64 b) {
    u64 d; asm("mul.rn.f32x2 %0, %1, %2;" : "=l"(d) : "l"(a), "l"(b)); return d;
}

// Normalized 1D Gaussian taps, win=11, sigma=1.5 (standard SSIM window, symmetric).
#define G0 0.00102838f
#define G1 0.00759876f
#define G2 0.03600077f
#define G3 0.10936069f
#define G4 0.21300553f
#define G5 0.26601172f

__global__ void __launch_bounds__(NTHREADS, 3)
ssim_main_kernel(const float* __restrict__ x,
                 const float* __restrict__ y,
                 float* __restrict__ out)
{
    __shared__ u64   hmu[HROWS * HSTRIDE];   // h-conv packed {mu_s, mu_d}
    __shared__ u64   hsq[HROWS * HSTRIDE];   // h-conv packed {E[s2], E[d2]}
    __shared__ float warpsum[NTHREADS / 32];

    const int tid = threadIdx.x;

    const u64 gg[6] = { pack2(G0,G0), pack2(G1,G1), pack2(G2,G2),
                        pack2(G3,G3), pack2(G4,G4), pack2(G5,G5) };
#define GG(k) gg[(k) < 6 ? (k) : 10 - (k)]

    const int n      = blockIdx.z;
    const int tile_x = blockIdx.x * TILE_W;
    const int tile_y = blockIdx.y * TILE_H;
    const float* __restrict__ xb = x + (size_t)n * IMG * IMG;
    const float* __restrict__ yb = y + (size_t)n * IMG * IMG;

    // zero the pad row (row 64) read by the tail v-segment's fixed unroll
    if (tid < HSTRIDE) {
        hmu[INH * HSTRIDE + tid] = 0ull;
        hsq[INH * HSTRIDE + tid] = 0ull;
    }

    // ---- Stage B: horizontal pass. 64 rows x 4 segments of 8 outputs = 256 tasks,
    // exactly one task per thread (perfectly balanced). Inputs stream from global (L1).
    {
        const int row = tid >> 2;                // 0..63 (haloed row)
        const int s0  = (tid & 3) * 8;           // output segment start
        const int gr  = tile_y + row - WIN / 2;
        const int gc0 = tile_x + s0 - WIN / 2;   // first needed input col
        const int gcr = tile_x + s0 - 8;         // 8-aligned vector base (= gc0-3)

        u64 amu[8], asq[8];
        #pragma unroll
        for (int o = 0; o < 8; o++) { amu[o] = 0ull; asq[o] = 0ull; }

        if ((unsigned)gr < IMG) {
            const float* __restrict__ xr = xb + gr * IMG;
            const float* __restrict__ yr = yb + gr * IMG;
            if (gcr >= 0 && gcr + 23 < IMG) {
                const float4* __restrict__ xr4 = (const float4*)(xr + gcr);
                const float4* __restrict__ yr4 = (const float4*)(yr + gcr);
                #pragma unroll
                for (int q = 0; q < 6; q++) {
                    const float4 xv = xr4[q];
                    const float4 yv = yr4[q];
                    const float xe[4] = {xv.x, xv.y, xv.z, xv.w};
                    const float ye[4] = {yv.x, yv.y, yv.z, yv.w};
                    #pragma unroll
                    for (int e = 0; e < 4; e++) {
                        const int t = 4 * q + e - 3;   // input index in 18-window
                        if (t < 0 || t > 17) continue;
                        const u64 p  = pack2(xe[e] + ye[e], xe[e] - ye[e]);
                        const u64 p2 = mul2(p, p);
                        #pragma unroll
                        for (int o = 0; o < 8; o++) {
                            const int k = t - o;
                            if (k >= 0 && k < WIN) {
                                amu[o] = fma2(GG(k), p,  amu[o]);
                                asq[o] = fma2(GG(k), p2, asq[o]);
                            }
                        }
                    }
                }
            } else {
                #pragma unroll
                for (int t = 0; t < 18; t++) {
                    const int gc = gc0 + t;
                    float vx = 0.f, vy = 0.f;
                    if ((unsigned)gc < IMG) { vx = xr[gc]; vy = yr[gc]; }
                    const u64 p  = pack2(vx + vy, vx - vy);
                    const u64 p2 = mul2(p, p);
                    #pragma unroll
                    for (int o = 0; o < 8; o++) {
                        const int k = t - o;
                        if (k >= 0 && k < WIN) {
                            amu[o] = fma2(GG(k), p,  amu[o]);
                            asq[o] = fma2(GG(k), p2, asq[o]);
                        }
                    }
                }
            }
        }
        #pragma unroll
        for (int o = 0; o < 8; o += 2) {
            *(ulonglong2*)&hmu[row * HSTRIDE + s0 + o] = make_ulonglong2(amu[o], amu[o + 1]);
            *(ulonglong2*)&hsq[row * HSTRIDE + s0 + o] = make_ulonglong2(asq[o], asq[o + 1]);
        }
    }
    __syncthreads();

    // ---- Stage C: vertical pass + SSIM. 8 segments x 32 cols = 256 threads.
    // Segments 0..5 own 7 rows, segments 6..7 own 6 rows (6*7 + 2*6 = 54).
    const float C1  = 1e-4f;
    const float C2  = 9e-4f;
    const float EPS = 1e-8f;

    float local = 0.f;
    {
        const int col  = tid & 31;
        const int seg  = tid >> 5;                         // 0..7
        const int r0   = (seg < 6) ? seg * 7 : 42 + (seg - 6) * 6;
        const int nout = (seg < 6) ? 7 : 6;

        u64 vmu[7], vsq[7];
        #pragma unroll
        for (int o = 0; o < 7; o++) { vmu[o] = 0ull; vsq[o] = 0ull; }

        #pragma unroll
        for (int i = 0; i < 17; i++) {                     // rows r0..r0+16 (pad row ok)
            const u64 m = hmu[(r0 + i) * HSTRIDE + col];
            const u64 q = hsq[(r0 + i) * HSTRIDE + col];
            #pragma unroll
            for (int o = 0; o < 7; o++) {
                const int k = i - o;
                if (k >= 0 && k < WIN) {
                    vmu[o] = fma2(GG(k), m, vmu[o]);
                    vsq[o] = fma2(GG(k), q, vsq[o]);
                }
            }
        }

        #pragma unroll
        for (int o = 0; o < 7; o++) {
            if (o < nout && (tile_y + r0 + o) < IMG) {
                float a, b, e, f;
                const u64 q2 = mul2(vmu[o], vmu[o]);   // {mu_s^2, mu_d^2}
                unpack2(q2, a, b);
                unpack2(vsq[o], e, f);                 // {E[s2], E[d2]}
                const float P  = 0.5f * (a - b);       // 2*mu_x*mu_y
                const float Qm = 0.5f * (a + b);       // mu_x^2 + mu_y^2
                const float R  = 0.5f * (e - f) - P;   // 2*sig_xy
                const float S  = 0.5f * (e + f) - Qm;  // sig_x^2 + sig_y^2
                const float num = (P + C1) * (R + C2);
                const float den = (Qm + C1) * (S + C2);
                float v = __fdividef(num, den + EPS);
                v = fminf(fmaxf(v, 0.f), 1.f);
                local += v;
            }
        }
    }

    // ---- Block reduction
    #pragma unroll
    for (int off = 16; off; off >>= 1)
        local += __shfl_down_sync(0xffffffffu, local, off);
    if ((tid & 31) == 0) warpsum[tid >> 5] = local;
    __syncthreads();

    // ---- Fused finale: self-resetting device accumulator, last CTA writes out.
    if (tid == 0) {
        float s = 0.f;
        #pragma unroll
        for (int i = 0; i < NTHREADS / 32; i++) s += warpsum[i];
        atomicAdd(&g_acc, (double)s);
        __threadfence();
        const unsigned done = atomicAdd(&g_count, 1u);
        if (done == NBLOCKS - 1) {
            __threadfence();
            const double v = *(volatile double*)&g_acc;
            out[0] = (float)(v / ((double)NIMG * IMG * IMG));
            *(volatile double*)&g_acc = 0.0;            // reset for next replay
            __threadfence();
            *(volatile unsigned*)&g_count = 0u;
        }
    }
}

extern "C" void kernel_launch(void* const* d_in, const int* in_sizes, int n_in,
                              void* d_out, int out_size)
{
    const float* x = (const float*)d_in[0];
    const float* y = (const float*)d_in[1];
    float* out = (float*)d_out;

    dim3 grid(IMG / TILE_W, GRID_Y, NIMG);   // 16 x 10 x 32 = 5120 CTAs
    ssim_main_kernel<<<grid, NTHREADS>>>(x, y, out);
}